// round 12
// baseline (speedup 1.0000x reference)
#include <cuda_runtime.h>
#include <cstdint>

#define FDIM 1024
#define CDIM 64
#define NROWS 65536
#define TR 16                         // rows per tile
#define NTILES (NROWS / TR)           // 4096
#define NTHREADS 256
#define NBLOCKS (148 * 3)
#define ROWSTRIDE 1028                // floats = 4112 B (16B aligned)
#define MAXPADF 1280
#define MAXK (MAXPADF / 2)            // 640

#define NEG_INF __int_as_float(0xff800000)

// smem layout (bytes): [0:8) mbar | [16:64) swk | [64:2112) comb[4][8][16]
//                      [2112:4672) skmeta | [4672:+65792) tile
#define SMEM_COMB   64
#define SMEM_KMETA  2112
#define SMEM_TILE   4672
#define SMEM_BYTES  (SMEM_TILE + TR * ROWSTRIDE * 4)

// meta bits per k-step: f0[0:10) pad0:10 f1[11:21) pad1:21 gid[22:28) newg:28

__device__ int    g_kmeta[MAXK];
__device__ int    g_wk[9];
__device__ double g_acc[64];

// ---------------------------------------------------------------------------
// Setup <<<1,256>>>: seg ids, 4-padded group-sorted order, packed k-step meta.
// ---------------------------------------------------------------------------
__global__ void setup_kernel(const float* __restrict__ mask) {
    __shared__ int scnt[CDIM];
    __shared__ int spstart[CDIM + 1];
    __shared__ int s_w0sum;
    __shared__ unsigned short ord[MAXPADF];
    __shared__ unsigned char  ggid[MAXPADF];
    const int t = threadIdx.x, lane = t & 31;

    if (t < CDIM) scnt[t] = 0;
    for (int i = t; i < MAXPADF; i += 256) ord[i] = 0xFFFF;
    __syncthreads();

    int segs[4], ranks[4];
#pragma unroll
    for (int i = 0; i < 4; i++) {
        int f = t + 256 * i;
        const float4* mrow = (const float4*)(mask + f * CDIM);
        float acc = 0.f;
#pragma unroll
        for (int q = 0; q < 16; q++) {
            float4 m = mrow[q];
            float c0 = (float)(4 * q);
            acc = fmaf(m.x, c0, acc);       acc = fmaf(m.y, c0 + 1.f, acc);
            acc = fmaf(m.z, c0 + 2.f, acc); acc = fmaf(m.w, c0 + 3.f, acc);
        }
        segs[i]  = (int)(acc + 0.5f);
        ranks[i] = atomicAdd(&scnt[segs[i]], 1);
    }
    __syncthreads();

    int v = 0, sc = 0;
    if (t < CDIM) {
        v = (scnt[t] + 3) & ~3;            // pad groups to multiple of 4
        sc = v;
#pragma unroll
        for (int o = 1; o < 32; o <<= 1) {
            int n = __shfl_up_sync(~0u, sc, o);
            if (lane >= o) sc += n;
        }
        if (t == 31) s_w0sum = sc;
    }
    __syncthreads();
    if (t < CDIM) {
        int base = sc - v + ((t >= 32) ? s_w0sum : 0);
        spstart[t] = base;
        if (t == 63) spstart[64] = base + v;
        g_acc[t] = 0.0;
    }
    __syncthreads();

#pragma unroll
    for (int i = 0; i < 4; i++) {
        int f = t + 256 * i;
        ord[spstart[segs[i]] + ranks[i]] = (unsigned short)f;
    }
    if (t < CDIM)
        for (int p = spstart[t]; p < spstart[t + 1]; p++)
            ggid[p] = (unsigned char)t;
    __syncthreads();

    const int K = spstart[64] >> 1;
    for (int k = t; k < MAXK; k += 256) {
        int m = 0;
        if (k < K) {
            unsigned f0 = ord[2 * k], f1 = ord[2 * k + 1];
            int pad0 = (f0 == 0xFFFFu); if (pad0) f0 = 0;
            int pad1 = (f1 == 0xFFFFu); if (pad1) f1 = 0;
            int gid  = ggid[2 * k];
            int newg = (k == 0) || (ggid[2 * k - 1] != gid);
            m = (int)(f0 | (pad0 << 10) | (f1 << 11) | (pad1 << 21)
                      | (gid << 22) | (newg << 28));
        }
        g_kmeta[k] = m;
    }
    if (t <= 8) g_wk[t] = spstart[8 * t] >> 1;
}

// ---------------------------------------------------------------------------
// Main: persistent; 16-row tiles loaded by cp.async.bulk (no LDG path).
// 8 warps x 8 groups each; lane = row(16) x stream(2); register-resident
// running group-max / total / label-sum over the sorted order.
// ---------------------------------------------------------------------------
__global__ void __launch_bounds__(NTHREADS, 3) mix_kernel(
    const float* __restrict__ logits,
    const int*   __restrict__ labels,
    float*       __restrict__ unused)
{
    extern __shared__ char smem[];
    int*   swk    = (int*)(smem + 16);
    float* comb   = (float*)(smem + SMEM_COMB);
    int*   skmeta = (int*)(smem + SMEM_KMETA);

    const int t = threadIdx.x, lane = t & 31, w = t >> 5;
    const int r = lane & 15, h = lane >> 4;

    uint32_t smem_base;
    asm("{ .reg .u64 tmp; cvta.to.shared.u64 tmp, %1; cvt.u32.u64 %0, tmp; }"
        : "=r"(smem_base) : "l"(smem));
    const uint32_t mbar_addr = smem_base;
    const uint32_t tile_addr = smem_base + SMEM_TILE;

    for (int i = t; i < MAXK; i += NTHREADS) skmeta[i] = g_kmeta[i];
    if (t < 9) swk[t] = g_wk[t];
    if (t == 0)
        asm volatile("mbarrier.init.shared.b64 [%0], %1;"
                     :: "r"(mbar_addr), "r"(1) : "memory");
    __syncthreads();

    const int k0 = swk[w], k1 = swk[w + 1];
    const float* myrow = (const float*)(smem + SMEM_TILE) + r * ROWSTRIDE;
    int phase = 0;

    for (int tile = blockIdx.x; tile < NTILES; tile += NBLOCKS) {
        if (t == 0) {
            asm volatile("mbarrier.arrive.expect_tx.shared.b64 _, [%0], %1;"
                         :: "r"(mbar_addr), "r"(TR * FDIM * 4) : "memory");
            const char* src = (const char*)(logits + (size_t)tile * TR * FDIM);
#pragma unroll
            for (int rr = 0; rr < TR; rr++)
                asm volatile(
                    "cp.async.bulk.shared::cluster.global.mbarrier::complete_tx::bytes "
                    "[%0], [%1], %2, [%3];"
                    :: "r"(tile_addr + rr * (ROWSTRIDE * 4)),
                       "l"(src + (size_t)rr * FDIM * 4),
                       "r"(FDIM * 4), "r"(mbar_addr) : "memory");
        }
        asm volatile(
            "{\n\t.reg .pred P;\n\t"
            "WL%=:\n\t"
            "mbarrier.try_wait.parity.acquire.cta.shared::cta.b64 P, [%0], %1;\n\t"
            "@P bra WD%=;\n\t"
            "bra WL%=;\n\t"
            "WD%=:\n\t}"
            :: "r"(mbar_addr), "r"(phase) : "memory");

        const int lab = labels[tile * TR + r];
        float tot = 0.f, ls = 0.f, S = 0.f, gm = NEG_INF, gml = NEG_INF;
        int prevgid = 255;

        for (int k = k0; k < k1; k++) {
            const int m = skmeta[k];
            if (m & (1 << 28)) {              // warp-uniform group boundary
                float gmf = fmaxf(gm, __shfl_xor_sync(~0u, gm, 16));
                S += __expf(gmf);
                if (prevgid == lab) gml = gmf;
                gm = NEG_INF;
            }
            const int gid = (m >> 22) & 63;
            prevgid = gid;
            const unsigned fb = (h == 0) ? ((unsigned)m & 0x7FFu)
                                         : (((unsigned)m >> 11) & 0x7FFu);
            float vv = myrow[fb & 1023u];
            if (fb >> 10) vv = NEG_INF;       // padding -> exp = 0, max no-op
            const float e = __expf(vv);
            tot += e;
            if (gid == lab) ls += e;
            gm = fmaxf(gm, vv);
        }
        {   // close last group
            float gmf = fmaxf(gm, __shfl_xor_sync(~0u, gm, 16));
            S += __expf(gmf);
            if (prevgid == lab) gml = gmf;
        }
        tot += __shfl_xor_sync(~0u, tot, 16);
        ls  += __shfl_xor_sync(~0u, ls, 16);

        if (h == 0) {
            comb[(0 * 8 + w) * 16 + r] = tot;
            comb[(1 * 8 + w) * 16 + r] = ls;
            comb[(2 * 8 + w) * 16 + r] = S;
            comb[(3 * 8 + w) * 16 + r] = gml;
        }
        __syncthreads();

        if (w == 0) {
            float loss = 0.f;
            if (h == 0) {
                float Ts = 0.f, Ls = 0.f, Ss = 0.f, G = NEG_INF;
#pragma unroll
                for (int ww = 0; ww < 8; ww++) {
                    Ts += comb[(0 * 8 + ww) * 16 + r];
                    Ls += comb[(1 * 8 + ww) * 16 + r];
                    Ss += comb[(2 * 8 + ww) * 16 + r];
                    G   = fmaxf(G, comb[(3 * 8 + ww) * 16 + r]);
                }
                loss = 0.5f * ((logf(Ss) - G) + (logf(Ts) - logf(Ls)));
            }
#pragma unroll
            for (int o = 16; o; o >>= 1)
                loss += __shfl_xor_sync(~0u, loss, o);
            if (lane == 0) atomicAdd(&g_acc[tile & 63], (double)loss);
        }
        __syncthreads();   // all reads done before next tile's bulk copies
        phase ^= 1;
    }
}

// ---------------------------------------------------------------------------
// Finalize: mean over rows -> d_out[0]
// ---------------------------------------------------------------------------
__global__ void finalize_kernel(float* __restrict__ out) {
    double s = 0.0;
#pragma unroll
    for (int i = 0; i < 64; i++) s += g_acc[i];
    out[0] = (float)(s / (double)NROWS);
}

extern "C" void kernel_launch(void* const* d_in, const int* in_sizes, int n_in,
                              void* d_out, int out_size) {
    const float* logits = (const float*)d_in[0];  // [32, 2048, 1024] f32
    const int*   labels = (const int*)d_in[1];    // [32, 2048] i32
    const float* mask   = (const float*)d_in[2];  // [1024, 64] f32

    cudaFuncSetAttribute(mix_kernel,
                         cudaFuncAttributeMaxDynamicSharedMemorySize, SMEM_BYTES);
    setup_kernel<<<1, 256>>>(mask);
    mix_kernel<<<NBLOCKS, NTHREADS, SMEM_BYTES>>>(logits, labels, (float*)d_out);
    finalize_kernel<<<1, 1>>>((float*)d_out);
}

// round 15
// speedup vs baseline: 1.2231x; 1.2231x over previous
#include <cuda_runtime.h>

#define FDIM 1024
#define CDIM 64
#define NROWS 65536
#define RPB 8                          // warps (row streams) per block
#define NTHREADS (RPB * 32)
#define NBLOCKS (148 * 4)              // persistent: 4 blocks/SM
#define NWARPS_TOTAL (NBLOCKS * RPB)
#define PADF 1216                      // padded sorted positions (1024 + 64*3)

#define NEG_INF __int_as_float(0xff800000)

// Scratch (no allocations allowed)
__device__ unsigned short g_meta16[FDIM];     // bank-matched sorted position per f
__device__ int            g_pstart[CDIM + 1]; // padded group boundaries
__device__ double         g_acc[64];          // interleaved loss accumulators

// ---------------------------------------------------------------------------
// Setup <<<1, 256>>>: seg ids via one-hot dot product, 4-padded group layout,
// then PER-GROUP BANK MATCHING: element f gets a position whose smem bank
// equals f's owning lane ((f>>2)&31) when available -> conflict-lean scatter.
// All loops are statically bounded (no unbounded while).
// ---------------------------------------------------------------------------
__global__ void setup_kernel(const float* __restrict__ mask) {
    __shared__ int            scnt[CDIM];
    __shared__ int            sbase[CDIM];
    __shared__ int            s_w0sum;
    __shared__ unsigned short ord[PADF];
    const int t = threadIdx.x, lane = t & 31;

    if (t < CDIM) scnt[t] = 0;
    __syncthreads();

    int segs[4], ranks[4];
#pragma unroll
    for (int i = 0; i < 4; i++) {
        int f = t + 256 * i;
        const float4* mrow = (const float4*)(mask + f * CDIM);
        float acc = 0.f;
#pragma unroll
        for (int q = 0; q < 16; q++) {
            float4 m = mrow[q];
            float c0 = (float)(4 * q);
            acc = fmaf(m.x, c0, acc);       acc = fmaf(m.y, c0 + 1.f, acc);
            acc = fmaf(m.z, c0 + 2.f, acc); acc = fmaf(m.w, c0 + 3.f, acc);
        }
        segs[i]  = (int)(acc + 0.5f);                 // one-hot argmax
        ranks[i] = atomicAdd(&scnt[segs[i]], 1);
    }
    __syncthreads();

    // exclusive prefix of 4-padded group counts
    int v = 0, sc = 0;
    if (t < CDIM) {
        v = (scnt[t] + 3) & ~3;
        sc = v;
#pragma unroll
        for (int o = 1; o < 32; o <<= 1) {
            int n = __shfl_up_sync(~0u, sc, o);
            if (lane >= o) sc += n;
        }
        if (t == 31) s_w0sum = sc;
    }
    __syncthreads();
    if (t < CDIM) {
        int base = sc - v + ((t >= 32) ? s_w0sum : 0);
        sbase[t] = base;
        g_pstart[t] = base;
        if (t == 63) g_pstart[64] = base + v;
        g_acc[t] = 0.0;                               // re-zero every replay
    }
    __syncthreads();

    // member lists per group (contiguous, arbitrary order)
#pragma unroll
    for (int i = 0; i < 4; i++)
        ord[sbase[segs[i]] + ranks[i]] = (unsigned short)(t + 256 * i);
    __syncthreads();

    // per-group bank matching (one group per thread, 64 threads)
    if (t < CDIM) {
        const int base = sbase[t];
        const int len  = scnt[t];
        if (len >= 1 && len <= 32) {
            const unsigned lenmask =
                (len == 32) ? 0xFFFFFFFFu : ((1u << len) - 1u);
            unsigned taken = 0;
            // pass 1: claim positions whose bank == owning lane
            for (int j = 0; j < len; j++) {
                int f = ord[base + j];
                int ln = (f >> 2) & 31;
                int i = (ln - base) & 31;               // pos base+i has bank ln
                if (i < len && !((taken >> i) & 1u)) {
                    g_meta16[f] = (unsigned short)(base + i);
                    taken |= 1u << i;
                    ord[base + j] = 0xFFFF;             // matched
                }
            }
            // pass 2: leftovers into lowest free slots (bounded, via ffs)
            for (int j = 0; j < len; j++) {
                int f = ord[base + j];
                if (f == 0xFFFF) continue;
                unsigned freebits = (~taken) & lenmask;
                int i = freebits ? (__ffs(freebits) - 1) : j;   // j = safe fallback
                g_meta16[f] = (unsigned short)(base + i);
                taken |= 1u << i;
            }
        } else {  // empty or oversize group: identity order fallback
            for (int j = 0; j < len; j++)
                g_meta16[ord[base + j]] = (unsigned short)(base + j);
        }
    }
}

// ---------------------------------------------------------------------------
// Main: persistent warp-per-row (proven R9 structure). Per row: 8 batched
// float4 LDG, exp + range-test label-sum + bank-matched scatter, aligned
// maskless float4 segment-max scan. 16-bit meta (ushort4 LDS.64).
// ---------------------------------------------------------------------------
__global__ void __launch_bounds__(NTHREADS, 4) mix_kernel(
    const float* __restrict__ logits,
    const int*   __restrict__ labels)
{
    __shared__ float          sslice[RPB][PADF];   // 38 KB padded sorted rows
    __shared__ unsigned short smeta16[FDIM];       // 2 KB positions
    __shared__ int            spstart[CDIM + 1];

    const int t    = threadIdx.x;
    const int lane = t & 31;
    const int w    = t >> 5;

    // block prologue
    reinterpret_cast<uint2*>(smeta16)[t] = reinterpret_cast<const uint2*>(g_meta16)[t];
    if (t <= CDIM) spstart[t] = g_pstart[t];
    __syncthreads();

    float*  my  = sslice[w];
    float4* my4 = reinterpret_cast<float4*>(my);
    for (int i = lane; i < PADF / 4; i += 32)      // pads stay -inf forever
        my4[i] = make_float4(NEG_INF, NEG_INF, NEG_INF, NEG_INF);
    __syncwarp();

    const int a0 = spstart[lane],      b0 = spstart[lane + 1];
    const int a1 = spstart[lane + 32], b1 = spstart[lane + 33];
    const ushort4* mp = reinterpret_cast<const ushort4*>(smeta16);

    for (int row = blockIdx.x * RPB + w; row < NROWS; row += NWARPS_TOTAL) {
        const int label = __ldg(&labels[row]);
        const unsigned lstart = (unsigned)spstart[label];
        const unsigned llen   = (unsigned)spstart[label + 1] - lstart;

        const float4* rp = reinterpret_cast<const float4*>(logits + (size_t)row * FDIM);
        float4 v0 = rp[lane];
        float4 v1 = rp[lane + 32];
        float4 v2 = rp[lane + 64];
        float4 v3 = rp[lane + 96];
        float4 v4 = rp[lane + 128];
        float4 v5 = rp[lane + 160];
        float4 v6 = rp[lane + 192];
        float4 v7 = rp[lane + 224];

        float tot = 0.0f, ls = 0.0f;

        // element in label group  <=>  pos - lstart < llen  (unsigned)
#define DO_CHUNK(VV, CI)                                                     \
        {                                                                    \
            ushort4 m = mp[lane + 32 * (CI)];                                \
            { float e = __expf(VV.x); tot += e;                              \
              if ((unsigned)m.x - lstart < llen) ls += e;  my[m.x] = VV.x; } \
            { float e = __expf(VV.y); tot += e;                              \
              if ((unsigned)m.y - lstart < llen) ls += e;  my[m.y] = VV.y; } \
            { float e = __expf(VV.z); tot += e;                              \
              if ((unsigned)m.z - lstart < llen) ls += e;  my[m.z] = VV.z; } \
            { float e = __expf(VV.w); tot += e;                              \
              if ((unsigned)m.w - lstart < llen) ls += e;  my[m.w] = VV.w; } \
        }
        DO_CHUNK(v0, 0) DO_CHUNK(v1, 1) DO_CHUNK(v2, 2) DO_CHUNK(v3, 3)
        DO_CHUNK(v4, 4) DO_CHUNK(v5, 5) DO_CHUNK(v6, 6) DO_CHUNK(v7, 7)
#undef DO_CHUNK

        __syncwarp();   // scatter -> scan

        // aligned maskless segment max: lane handles groups lane, lane+32
        float gm0 = NEG_INF, gm1 = NEG_INF;
        for (int q = a0 >> 2; q < (b0 >> 2); q++) {
            float4 c = my4[q];
            gm0 = fmaxf(gm0, fmaxf(fmaxf(c.x, c.y), fmaxf(c.z, c.w)));
        }
        for (int q = a1 >> 2; q < (b1 >> 2); q++) {
            float4 c = my4[q];
            gm1 = fmaxf(gm1, fmaxf(fmaxf(c.x, c.y), fmaxf(c.z, c.w)));
        }
        __syncwarp();   // scan done before next row's scatter

        float cand = (label < 32) ? gm0 : gm1;
        float gml  = __shfl_sync(~0u, cand, label & 31);

        float csum = __expf(gm0) + __expf(gm1);
#pragma unroll
        for (int o = 16; o; o >>= 1) {
            csum += __shfl_xor_sync(~0u, csum, o);
            tot  += __shfl_xor_sync(~0u, tot, o);
            ls   += __shfl_xor_sync(~0u, ls, o);
        }

        if (lane == 0) {
            float ce  = logf(csum) - gml;        // lse(coarse_max) - gmax[label]
            float nll = logf(tot) - logf(ls);    // log(total) - log(group_sum)
            atomicAdd(&g_acc[row & 63], (double)(0.5f * (ce + nll)));
        }
    }
}

// ---------------------------------------------------------------------------
// Finalize: mean over rows -> d_out[0]
// ---------------------------------------------------------------------------
__global__ void finalize_kernel(float* __restrict__ out) {
    double s = 0.0;
#pragma unroll
    for (int i = 0; i < 64; i++) s += g_acc[i];
    out[0] = (float)(s / (double)NROWS);
}

extern "C" void kernel_launch(void* const* d_in, const int* in_sizes, int n_in,
                              void* d_out, int out_size) {
    const float* logits = (const float*)d_in[0];  // [32, 2048, 1024] f32
    const int*   labels = (const int*)d_in[1];    // [32, 2048] i32
    const float* mask   = (const float*)d_in[2];  // [1024, 64] f32

    setup_kernel<<<1, 256>>>(mask);
    mix_kernel<<<NBLOCKS, NTHREADS>>>(logits, labels);
    finalize_kernel<<<1, 1>>>((float*)d_out);
}